// round 2
// baseline (speedup 1.0000x reference)
#include <cuda_runtime.h>
#include <math.h>

// EarthAttention3D (Pangu-Weather windowed attention), fixed shapes:
//   B_=960 windows, L=144, C=192, HEADS=6, hd=32, W_WINS=15, NW=64
#define BWIN 960
#define LTOK 144
#define CDIM 192
#define NH   6
#define HDM  32
#define WWINS 15
#define TABNW 64

// Scratch (static device globals; no runtime allocation allowed)
__device__ float g_qkv[(size_t)BWIN * LTOK * 3 * CDIM];          // (960,144,576)
__device__ float g_att[(size_t)BWIN * LTOK * CDIM];              // (960,144,192)
__device__ float g_pre[(size_t)TABNW * NH * LTOK * LTOK];        // (64,6,144,144) gathered bias

// ---------------------------------------------------------------------------
// f32x2 packed helpers
// ---------------------------------------------------------------------------
__device__ __forceinline__ void ffma2(unsigned long long& acc,
                                      unsigned long long a,
                                      unsigned long long b) {
    asm("fma.rn.f32x2 %0, %1, %2, %0;" : "+l"(acc) : "l"(a), "l"(b));
}
__device__ __forceinline__ float2 unpack2(unsigned long long v) {
    float2 r;
    asm("mov.b64 {%0, %1}, %2;" : "=f"(r.x), "=f"(r.y) : "l"(v));
    return r;
}

// ---------------------------------------------------------------------------
// Packed-fp32 GEMM:  C[M,N] = A[M,K] @ B[K,N] + bias[N]
// Tile 128x64, BK=16, 128 threads; per-thread 8 rows x 8 cols using f32x2:
//   row pairs packed (A transposed in smem), B duplicated in smem.
// Requires 128|M, 64|N, 16|K.
// ---------------------------------------------------------------------------
#define APITCH 132   // AsT row pitch (floats)
#define BPITCH 132   // Bd row pitch (floats)

__global__ void __launch_bounds__(128) gemm_f32x2_kernel(
    const float* __restrict__ A, const float* __restrict__ B,
    const float* __restrict__ bias, float* __restrict__ C,
    int M, int N, int K)
{
    __shared__ float AsT[16 * APITCH];   // [kk][row] (transposed A tile: rows contiguous)
    __shared__ float Bd[16 * BPITCH];    // [kk][2*col] duplicated B tile

    const int tid  = threadIdx.x;
    const int tx   = tid & 7;            // 8 col-groups
    const int ty   = tid >> 3;           // 16 row-groups
    const int ty8  = ty * 8;
    const int c0   = tx * 8;
    const int row0 = blockIdx.y << 7;
    const int col0 = blockIdx.x << 6;

    unsigned long long acc[4][8];
#pragma unroll
    for (int i = 0; i < 4; ++i)
#pragma unroll
        for (int j = 0; j < 8; ++j) acc[i][j] = 0ull;

    // loader indices
    const int lr  = tid >> 2;            // A: row within tile (two rows per 4 lanes? no: chunk scheme)
    const int lkq = tid & 3;             // A: k-quad
    const int bkk = tid >> 3;            // B: k row
    const int bc0 = (tid & 7) * 8;       // B: col start

    for (int kt = 0; kt < K; kt += 16) {
        // ---- load A tile (128x16) transposed into AsT ----
#pragma unroll
        for (int i = 0; i < 4; ++i) {
            int ch = tid + (i << 7);     // 0..511
            int r  = ch >> 2;            // 0..127
            int kq = ch & 3;             // 0..3
            float4 a = *(const float4*)&A[(size_t)(row0 + r) * K + kt + kq * 4];
            AsT[(4 * kq + 0) * APITCH + r] = a.x;
            AsT[(4 * kq + 1) * APITCH + r] = a.y;
            AsT[(4 * kq + 2) * APITCH + r] = a.z;
            AsT[(4 * kq + 3) * APITCH + r] = a.w;
        }
        // ---- load B tile (16x64) duplicated into Bd ----
        {
            const float* bp = &B[(size_t)(kt + bkk) * N + col0 + bc0];
            float4 b0 = *(const float4*)&bp[0];
            float4 b1 = *(const float4*)&bp[4];
            *(float4*)&Bd[bkk * BPITCH + 2 * bc0 + 0]  = make_float4(b0.x, b0.x, b0.y, b0.y);
            *(float4*)&Bd[bkk * BPITCH + 2 * bc0 + 4]  = make_float4(b0.z, b0.z, b0.w, b0.w);
            *(float4*)&Bd[bkk * BPITCH + 2 * bc0 + 8]  = make_float4(b1.x, b1.x, b1.y, b1.y);
            *(float4*)&Bd[bkk * BPITCH + 2 * bc0 + 12] = make_float4(b1.z, b1.z, b1.w, b1.w);
        }
        __syncthreads();

#pragma unroll
        for (int kk = 0; kk < 16; ++kk) {
            ulonglong2 a01 = *(const ulonglong2*)&AsT[kk * APITCH + ty8];      // row pairs 0,1
            ulonglong2 a23 = *(const ulonglong2*)&AsT[kk * APITCH + ty8 + 4];  // row pairs 2,3
            ulonglong2 q0  = *(const ulonglong2*)&Bd[kk * BPITCH + 2 * c0 + 0];
            ulonglong2 q1  = *(const ulonglong2*)&Bd[kk * BPITCH + 2 * c0 + 4];
            ulonglong2 q2  = *(const ulonglong2*)&Bd[kk * BPITCH + 2 * c0 + 8];
            ulonglong2 q3  = *(const ulonglong2*)&Bd[kk * BPITCH + 2 * c0 + 12];
            unsigned long long ar[4] = {a01.x, a01.y, a23.x, a23.y};
            unsigned long long bd[8] = {q0.x, q0.y, q1.x, q1.y, q2.x, q2.y, q3.x, q3.y};
#pragma unroll
            for (int r2 = 0; r2 < 4; ++r2)
#pragma unroll
                for (int j = 0; j < 8; ++j)
                    ffma2(acc[r2][j], ar[r2], bd[j]);
        }
        __syncthreads();
    }

    // epilogue: unpack pairs, add bias, store
    float bb[8];
    *(float4*)&bb[0] = *(const float4*)&bias[col0 + c0];
    *(float4*)&bb[4] = *(const float4*)&bias[col0 + c0 + 4];
#pragma unroll
    for (int r2 = 0; r2 < 4; ++r2) {
        float lo[8], hi[8];
#pragma unroll
        for (int j = 0; j < 8; ++j) {
            float2 u = unpack2(acc[r2][j]);
            lo[j] = u.x + bb[j];
            hi[j] = u.y + bb[j];
        }
        float* crow0 = &C[(size_t)(row0 + ty8 + 2 * r2) * N + col0 + c0];
        float* crow1 = crow0 + N;
        *(float4*)&crow0[0] = make_float4(lo[0], lo[1], lo[2], lo[3]);
        *(float4*)&crow0[4] = make_float4(lo[4], lo[5], lo[6], lo[7]);
        *(float4*)&crow1[0] = make_float4(hi[0], hi[1], hi[2], hi[3]);
        *(float4*)&crow1[4] = make_float4(hi[4], hi[5], hi[6], hi[7]);
    }
}

// ---------------------------------------------------------------------------
// Pre-gather earth bias: pre[grp][head][l][m] = bias_table[pos[l][m]][grp][head]
// ---------------------------------------------------------------------------
__global__ void __launch_bounds__(256) bias_pre_kernel(
    const float* __restrict__ bt, const int* __restrict__ pos,
    float* __restrict__ pre)
{
    const int gh   = blockIdx.x;            // 0..383 = grp*6+head
    const int grp  = gh / NH;
    const int head = gh - grp * NH;
    float* dst = pre + (size_t)gh * LTOK * LTOK;
    for (int i = threadIdx.x; i < LTOK * LTOK; i += 256) {
        int pi = pos[i];
        dst[i] = bt[(size_t)pi * (TABNW * NH) + grp * NH + head];
    }
}

// ---------------------------------------------------------------------------
// Fused attention per (window, head):
//   S = scale*Q @ K^T + pre[grp,head] + mask[wi]; P = softmax(S); out = P @ V
// 256 threads = 8 warps; warp owns 18 rows in 3 passes of 6.
// ---------------------------------------------------------------------------
#define QKV_PITCH 36   // Q/K smem row pitch
#define VT_PITCH 148   // V^T row pitch (per head-dim)

__global__ void __launch_bounds__(256, 2) attn_kernel(
    const float* __restrict__ qkv, const float* __restrict__ mask,
    const float* __restrict__ pre, float* __restrict__ att)
{
    const int wi   = blockIdx.x;      // 0..959 (consecutive blocks share grp -> L2 reuse of pre)
    const int head = blockIdx.y;      // 0..5
    const int grp  = wi / WWINS;
    const int tid  = threadIdx.x;
    const int w    = tid >> 5;
    const int lane = tid & 31;

    extern __shared__ float sm[];
    float* Qs = sm;                         // 144*36
    float* Ks = Qs + LTOK * QKV_PITCH;      // 144*36
    float* VT = Ks + LTOK * QKV_PITCH;      // 32*148  (V transposed: [d][m])
    float* Pb = VT + HDM * VT_PITCH;        // 8 warps * 6 rows * 144

    const float scale = 0.17677669529663687f;  // 32^-0.5
    const float* qbase = qkv + (size_t)wi * LTOK * (3 * CDIM) + head * HDM;

    for (int i = tid; i < LTOK * HDM; i += 256) {
        int l = i >> 5;
        int d = i & 31;
        const float* p = qbase + (size_t)l * (3 * CDIM);
        Qs[l * QKV_PITCH + d] = p[d] * scale;
        Ks[l * QKV_PITCH + d] = p[CDIM + d];
        VT[d * VT_PITCH + l]  = p[2 * CDIM + d];
    }
    __syncthreads();

    const float* mrow = mask + (size_t)wi * LTOK * LTOK;
    const float* prow_bias = pre + (size_t)(grp * NH + head) * LTOK * LTOK;
    float* prow = Pb + w * 6 * LTOK;
    const int l0 = w * 18;

    for (int pass = 0; pass < 3; ++pass) {
        const int lbase = l0 + pass * 6;

        // ---- S = scale*Q @ K^T (6 rows x 5 m-slots per lane) ----
        float acc[6][5];
#pragma unroll
        for (int r = 0; r < 6; ++r)
#pragma unroll
            for (int j = 0; j < 5; ++j) acc[r][j] = 0.f;

#pragma unroll
        for (int dc = 0; dc < 8; ++dc) {
            float4 kv[5];
#pragma unroll
            for (int j = 0; j < 5; ++j) {
                int m = lane + 32 * j;
                kv[j] = (m < LTOK)
                    ? *(const float4*)&Ks[m * QKV_PITCH + dc * 4]
                    : make_float4(0.f, 0.f, 0.f, 0.f);
            }
#pragma unroll
            for (int r = 0; r < 6; ++r) {
                float4 qv = *(const float4*)&Qs[(lbase + r) * QKV_PITCH + dc * 4];
#pragma unroll
                for (int j = 0; j < 5; ++j) {
                    acc[r][j] += qv.x * kv[j].x + qv.y * kv[j].y
                               + qv.z * kv[j].z + qv.w * kv[j].w;
                }
            }
        }

        // ---- bias + mask + softmax per row, write P to warp buffer ----
#pragma unroll
        for (int r = 0; r < 6; ++r) {
            const int l = lbase + r;
            float s[5];
#pragma unroll
            for (int j = 0; j < 5; ++j) {
                int m = lane + 32 * j;
                if (m < LTOK) {
                    s[j] = acc[r][j] + prow_bias[l * LTOK + m] + mrow[l * LTOK + m];
                } else {
                    s[j] = -1e30f;
                }
            }
            float mx = s[0];
#pragma unroll
            for (int j = 1; j < 5; ++j) mx = fmaxf(mx, s[j]);
#pragma unroll
            for (int o = 16; o; o >>= 1)
                mx = fmaxf(mx, __shfl_xor_sync(0xffffffffu, mx, o));

            float sum = 0.f;
#pragma unroll
            for (int j = 0; j < 5; ++j) {
                float e = __expf(s[j] - mx);   // -1e30 underflows to 0
                s[j] = e;
                sum += e;
            }
#pragma unroll
            for (int o = 16; o; o >>= 1)
                sum += __shfl_xor_sync(0xffffffffu, sum, o);
            float inv = 1.0f / sum;
#pragma unroll
            for (int j = 0; j < 5; ++j) {
                int m = lane + 32 * j;
                if (m < LTOK) prow[r * LTOK + m] = s[j] * inv;
            }
        }
        __syncwarp();

        // ---- out = P @ V ; lane = output dim d ----
        float oacc[6] = {0.f, 0.f, 0.f, 0.f, 0.f, 0.f};
        const float* vt = &VT[lane * VT_PITCH];
        for (int m = 0; m < LTOK; m += 4) {
            float4 v = *(const float4*)&vt[m];
#pragma unroll
            for (int r = 0; r < 6; ++r) {
                float4 p = *(const float4*)&prow[r * LTOK + m];
                oacc[r] += p.x * v.x + p.y * v.y + p.z * v.z + p.w * v.w;
            }
        }
        float* obase = att + (size_t)wi * LTOK * CDIM + head * HDM + lane;
#pragma unroll
        for (int r = 0; r < 6; ++r)
            obase[(size_t)(lbase + r) * CDIM] = oacc[r];
        __syncwarp();   // prow reused next pass
    }
}

// ---------------------------------------------------------------------------
extern "C" void kernel_launch(void* const* d_in, const int* in_sizes, int n_in,
                              void* d_out, int out_size)
{
    const float* x          = (const float*)d_in[0];  // (960,144,192)
    const float* mask       = (const float*)d_in[1];  // (960,144,144)
    const float* W1         = (const float*)d_in[2];  // (192,576)
    const float* b1         = (const float*)d_in[3];  // (576,)
    const float* W2         = (const float*)d_in[4];  // (192,192)
    const float* b2         = (const float*)d_in[5];  // (192,)
    const float* bias_table = (const float*)d_in[6];  // (3312,64,6)
    const int*   pos        = (const int*)d_in[7];    // (144,144)
    float* out = (float*)d_out;

    void *qkv_p, *att_p, *pre_p;
    cudaGetSymbolAddress(&qkv_p, g_qkv);
    cudaGetSymbolAddress(&att_p, g_att);
    cudaGetSymbolAddress(&pre_p, g_pre);
    float* qkv = (float*)qkv_p;
    float* att = (float*)att_p;
    float* pre = (float*)pre_p;

    const int M = BWIN * LTOK;  // 138240

    const int attn_smem =
        (2 * LTOK * QKV_PITCH + HDM * VT_PITCH + 8 * 6 * LTOK) * (int)sizeof(float);
    cudaFuncSetAttribute(attn_kernel, cudaFuncAttributeMaxDynamicSharedMemorySize, attn_smem);

    // 0) gather earth bias -> dense (grp, head, l, m)
    bias_pre_kernel<<<TABNW * NH, 256>>>(bias_table, pos, pre);

    // 1) QKV projection: (138240,192) @ (192,576) + b1
    {
        dim3 grid(3 * CDIM / 64, M / 128);  // (9, 1080)
        gemm_f32x2_kernel<<<grid, 128>>>(x, W1, b1, qkv, M, 3 * CDIM, CDIM);
    }
    // 2) Fused windowed attention
    {
        dim3 grid(BWIN, NH);               // (960, 6)
        attn_kernel<<<grid, 256, attn_smem>>>(qkv, mask, pre, att);
    }
    // 3) Output projection: (138240,192) @ (192,192) + b2
    {
        dim3 grid(CDIM / 64, M / 128);     // (3, 1080)
        gemm_f32x2_kernel<<<grid, 128>>>(att, W2, b2, out, M, CDIM, CDIM);
    }
}

// round 4
// speedup vs baseline: 1.9965x; 1.9965x over previous
#include <cuda_runtime.h>
#include <math.h>

// EarthAttention3D (Pangu-Weather windowed attention), fixed shapes:
//   B_=960 windows, L=144, C=192, HEADS=6, hd=32, W_WINS=15, NW=64
#define BWIN 960
#define LTOK 144
#define CDIM 192
#define NH   6
#define HDM  32
#define WWINS 15
#define TABNW 64

// Scratch (static device globals; no runtime allocation allowed)
__device__ float g_qkv[(size_t)BWIN * LTOK * 3 * CDIM];          // (960,144,576)
__device__ float g_att[(size_t)BWIN * LTOK * CDIM];              // (960,144,192)
__device__ float g_pre[(size_t)TABNW * NH * LTOK * LTOK];        // (64,6,144,144) gathered bias

// ---------------------------------------------------------------------------
// Scalar-FFMA GEMM:  C[M,N] = A[M,K] @ B[K,N] + bias[N]
// Block tile 256x64, BK=16, 256 threads, 8x8 micro-tile per thread.
// A stored transposed in smem ([kk][row], pitch 260) so the micro-tile reads
// A as float4; per k-step: 4 LDS.128 feed 64 FFMAs -> FMA-issue bound.
// Requires 256|M, 64|N, 16|K  (M=138240=256*540, N in {576,192}, K=192).
// ---------------------------------------------------------------------------
#define APITCH 260   // 260*4 bytes % 16 == 0 (float4-aligned rows), low STS conflict

__global__ void __launch_bounds__(256, 2) gemm_kernel(
    const float* __restrict__ A, const float* __restrict__ B,
    const float* __restrict__ bias, float* __restrict__ C,
    int M, int N, int K)
{
    __shared__ float AsT[16 * APITCH];   // [kk][row 0..255]
    __shared__ float Bs[16 * 64];        // [kk][col 0..63]

    const int tid  = threadIdx.x;
    const int tx   = tid & 7;            // 8 col groups
    const int ty   = tid >> 3;           // 32 row groups
    const int ty4  = ty * 4;
    const int c0   = tx * 4;
    const int row0 = blockIdx.y << 8;
    const int col0 = blockIdx.x << 6;

    float acc[8][8];
#pragma unroll
    for (int i = 0; i < 8; ++i)
#pragma unroll
        for (int j = 0; j < 8; ++j) acc[i][j] = 0.f;

    const int bkk = tid >> 4;            // B loader: k row 0..15
    const int bc  = (tid & 15) * 4;      // B loader: col 0..60

    for (int kt = 0; kt < K; kt += 16) {
        // ---- load A tile (256x16) transposed ----
#pragma unroll
        for (int ch = 0; ch < 4; ++ch) {
            int idx = tid + (ch << 8);   // 0..1023
            int r   = idx >> 2;          // 0..255
            int kq  = idx & 3;           // 0..3
            float4 a = *(const float4*)&A[(size_t)(row0 + r) * K + kt + kq * 4];
            AsT[(kq * 4 + 0) * APITCH + r] = a.x;
            AsT[(kq * 4 + 1) * APITCH + r] = a.y;
            AsT[(kq * 4 + 2) * APITCH + r] = a.z;
            AsT[(kq * 4 + 3) * APITCH + r] = a.w;
        }
        // ---- load B tile (16x64) ----
        *(float4*)&Bs[bkk * 64 + bc] =
            *(const float4*)&B[(size_t)(kt + bkk) * N + col0 + bc];
        __syncthreads();

#pragma unroll
        for (int kk = 0; kk < 16; ++kk) {
            float4 a0 = *(const float4*)&AsT[kk * APITCH + ty4];
            float4 a1 = *(const float4*)&AsT[kk * APITCH + 128 + ty4];
            float4 b0 = *(const float4*)&Bs[kk * 64 + c0];
            float4 b1 = *(const float4*)&Bs[kk * 64 + 32 + c0];
            float av[8] = {a0.x, a0.y, a0.z, a0.w, a1.x, a1.y, a1.z, a1.w};
            float bv[8] = {b0.x, b0.y, b0.z, b0.w, b1.x, b1.y, b1.z, b1.w};
#pragma unroll
            for (int i = 0; i < 8; ++i)
#pragma unroll
                for (int j = 0; j < 8; ++j)
                    acc[i][j] += av[i] * bv[j];
        }
        __syncthreads();
    }

    // ---- epilogue: + bias, store (rows ty4..ty4+3 and +128; cols c0, c0+32)
    float4 bb0 = *(const float4*)&bias[col0 + c0];
    float4 bb1 = *(const float4*)&bias[col0 + 32 + c0];
#pragma unroll
    for (int i = 0; i < 8; ++i) {
        int r = row0 + ((i < 4) ? (ty4 + i) : (128 + ty4 + i - 4));
        float* crow = &C[(size_t)r * N + col0];
        float4 o0 = make_float4(acc[i][0] + bb0.x, acc[i][1] + bb0.y,
                                acc[i][2] + bb0.z, acc[i][3] + bb0.w);
        float4 o1 = make_float4(acc[i][4] + bb1.x, acc[i][5] + bb1.y,
                                acc[i][6] + bb1.z, acc[i][7] + bb1.w);
        *(float4*)&crow[c0]      = o0;
        *(float4*)&crow[32 + c0] = o1;
    }
}

// ---------------------------------------------------------------------------
// Pre-gather earth bias: pre[grp][head][l][m] = bias_table[pos[l][m]][grp][head]
// ---------------------------------------------------------------------------
__global__ void __launch_bounds__(256) bias_pre_kernel(
    const float* __restrict__ bt, const int* __restrict__ pos,
    float* __restrict__ pre)
{
    const int gh   = blockIdx.x;            // 0..383 = grp*6+head
    const int grp  = gh / NH;
    const int head = gh - grp * NH;
    float* dst = pre + (size_t)gh * LTOK * LTOK;
    for (int i = threadIdx.x; i < LTOK * LTOK; i += 256) {
        int pi = pos[i];
        dst[i] = bt[(size_t)pi * (TABNW * NH) + grp * NH + head];
    }
}

// ---------------------------------------------------------------------------
// Fused attention per (window, head):
//   S = scale*Q @ K^T + pre[grp,head] + mask[wi]; P = softmax(S); out = P @ V
// 256 threads = 8 warps; warp owns 18 rows in 3 passes of 6.
// ---------------------------------------------------------------------------
#define QKV_PITCH 36   // Q/K smem row pitch
#define VT_PITCH 148   // V^T row pitch (per head-dim)

__global__ void __launch_bounds__(256, 2) attn_kernel(
    const float* __restrict__ qkv, const float* __restrict__ mask,
    const float* __restrict__ pre, float* __restrict__ att)
{
    const int wi   = blockIdx.x;      // 0..959
    const int head = blockIdx.y;      // 0..5
    const int grp  = wi / WWINS;
    const int tid  = threadIdx.x;
    const int w    = tid >> 5;
    const int lane = tid & 31;

    extern __shared__ float sm[];
    float* Qs = sm;                         // 144*36
    float* Ks = Qs + LTOK * QKV_PITCH;      // 144*36
    float* VT = Ks + LTOK * QKV_PITCH;      // 32*148  (V transposed: [d][m])
    float* Pb = VT + HDM * VT_PITCH;        // 8 warps * 6 rows * 144

    const float scale = 0.17677669529663687f;  // 32^-0.5
    const float* qbase = qkv + (size_t)wi * LTOK * (3 * CDIM) + head * HDM;

    for (int i = tid; i < LTOK * HDM; i += 256) {
        int l = i >> 5;
        int d = i & 31;
        const float* p = qbase + (size_t)l * (3 * CDIM);
        Qs[l * QKV_PITCH + d] = p[d] * scale;
        Ks[l * QKV_PITCH + d] = p[CDIM + d];
        VT[d * VT_PITCH + l]  = p[2 * CDIM + d];
    }
    __syncthreads();

    const float* mrow = mask + (size_t)wi * LTOK * LTOK;
    const float* prow_bias = pre + (size_t)(grp * NH + head) * LTOK * LTOK;
    float* prow = Pb + w * 6 * LTOK;
    const int l0 = w * 18;

    for (int pass = 0; pass < 3; ++pass) {
        const int lbase = l0 + pass * 6;

        // ---- S = scale*Q @ K^T (6 rows x 5 m-slots per lane) ----
        float acc[6][5];
#pragma unroll
        for (int r = 0; r < 6; ++r)
#pragma unroll
            for (int j = 0; j < 5; ++j) acc[r][j] = 0.f;

#pragma unroll
        for (int dc = 0; dc < 8; ++dc) {
            float4 kv[5];
#pragma unroll
            for (int j = 0; j < 5; ++j) {
                int m = lane + 32 * j;
                kv[j] = (m < LTOK)
                    ? *(const float4*)&Ks[m * QKV_PITCH + dc * 4]
                    : make_float4(0.f, 0.f, 0.f, 0.f);
            }
#pragma unroll
            for (int r = 0; r < 6; ++r) {
                float4 qv = *(const float4*)&Qs[(lbase + r) * QKV_PITCH + dc * 4];
#pragma unroll
                for (int j = 0; j < 5; ++j) {
                    acc[r][j] += qv.x * kv[j].x + qv.y * kv[j].y
                               + qv.z * kv[j].z + qv.w * kv[j].w;
                }
            }
        }

        // ---- bias + mask + softmax per row, write P to warp buffer ----
#pragma unroll
        for (int r = 0; r < 6; ++r) {
            const int l = lbase + r;
            float s[5];
#pragma unroll
            for (int j = 0; j < 5; ++j) {
                int m = lane + 32 * j;
                if (m < LTOK) {
                    s[j] = acc[r][j] + prow_bias[l * LTOK + m] + mrow[l * LTOK + m];
                } else {
                    s[j] = -1e30f;
                }
            }
            float mx = s[0];
#pragma unroll
            for (int j = 1; j < 5; ++j) mx = fmaxf(mx, s[j]);
#pragma unroll
            for (int o = 16; o; o >>= 1)
                mx = fmaxf(mx, __shfl_xor_sync(0xffffffffu, mx, o));

            float sum = 0.f;
#pragma unroll
            for (int j = 0; j < 5; ++j) {
                float e = __expf(s[j] - mx);   // -1e30 underflows to 0
                s[j] = e;
                sum += e;
            }
#pragma unroll
            for (int o = 16; o; o >>= 1)
                sum += __shfl_xor_sync(0xffffffffu, sum, o);
            float inv = 1.0f / sum;
#pragma unroll
            for (int j = 0; j < 5; ++j) {
                int m = lane + 32 * j;
                if (m < LTOK) prow[r * LTOK + m] = s[j] * inv;
            }
        }
        __syncwarp();

        // ---- out = P @ V ; lane = output dim d ----
        float oacc[6] = {0.f, 0.f, 0.f, 0.f, 0.f, 0.f};
        const float* vt = &VT[lane * VT_PITCH];
        for (int m = 0; m < LTOK; m += 4) {
            float4 v = *(const float4*)&vt[m];
#pragma unroll
            for (int r = 0; r < 6; ++r) {
                float4 p = *(const float4*)&prow[r * LTOK + m];
                oacc[r] += p.x * v.x + p.y * v.y + p.z * v.z + p.w * v.w;
            }
        }
        float* obase = att + (size_t)wi * LTOK * CDIM + head * HDM + lane;
#pragma unroll
        for (int r = 0; r < 6; ++r)
            obase[(size_t)(lbase + r) * CDIM] = oacc[r];
        __syncwarp();   // prow reused next pass
    }
}

// ---------------------------------------------------------------------------
extern "C" void kernel_launch(void* const* d_in, const int* in_sizes, int n_in,
                              void* d_out, int out_size)
{
    const float* x          = (const float*)d_in[0];  // (960,144,192)
    const float* mask       = (const float*)d_in[1];  // (960,144,144)
    const float* W1         = (const float*)d_in[2];  // (192,576)
    const float* b1         = (const float*)d_in[3];  // (576,)
    const float* W2         = (const float*)d_in[4];  // (192,192)
    const float* b2         = (const float*)d_in[5];  // (192,)
    const float* bias_table = (const float*)d_in[6];  // (3312,64,6)
    const int*   pos        = (const int*)d_in[7];    // (144,144)
    float* out = (float*)d_out;

    void *qkv_p, *att_p, *pre_p;
    cudaGetSymbolAddress(&qkv_p, g_qkv);
    cudaGetSymbolAddress(&att_p, g_att);
    cudaGetSymbolAddress(&pre_p, g_pre);
    float* qkv = (float*)qkv_p;
    float* att = (float*)att_p;
    float* pre = (float*)pre_p;

    const int M = BWIN * LTOK;  // 138240

    const int attn_smem =
        (2 * LTOK * QKV_PITCH + HDM * VT_PITCH + 8 * 6 * LTOK) * (int)sizeof(float);
    cudaFuncSetAttribute(attn_kernel, cudaFuncAttributeMaxDynamicSharedMemorySize, attn_smem);

    // 0) gather earth bias -> dense (grp, head, l, m)
    bias_pre_kernel<<<TABNW * NH, 256>>>(bias_table, pos, pre);

    // 1) QKV projection: (138240,192) @ (192,576) + b1
    {
        dim3 grid(3 * CDIM / 64, M / 256);  // (9, 540)
        gemm_kernel<<<grid, 256>>>(x, W1, b1, qkv, M, 3 * CDIM, CDIM);
    }
    // 2) Fused windowed attention
    {
        dim3 grid(BWIN, NH);                // (960, 6)
        attn_kernel<<<grid, 256, attn_smem>>>(qkv, mask, pre, att);
    }
    // 3) Output projection: (138240,192) @ (192,192) + b2
    {
        dim3 grid(CDIM / 64, M / 256);      // (3, 540)
        gemm_kernel<<<grid, 256>>>(att, W2, b2, out, M, CDIM, CDIM);
    }
}

// round 5
// speedup vs baseline: 2.0148x; 1.0092x over previous
#include <cuda_runtime.h>
#include <math.h>

// EarthAttention3D (Pangu-Weather windowed attention), fixed shapes:
//   B_=960 windows, L=144, C=192, HEADS=6, hd=32, W_WINS=15, NW=64
#define BWIN 960
#define LTOK 144
#define CDIM 192
#define NH   6
#define HDM  32
#define WWINS 15
#define TABNW 64

// Scratch (static device globals; no runtime allocation allowed)
__device__ float g_qkv[(size_t)BWIN * LTOK * 3 * CDIM];          // (960,144,576)
__device__ float g_att[(size_t)BWIN * LTOK * CDIM];              // (960,144,192)
__device__ float g_pre[(size_t)TABNW * NH * LTOK * LTOK];        // (64,6,144,144) gathered bias

// ---------------------------------------------------------------------------
// Scalar-FFMA GEMM:  C[M,N] = A[M,K] @ B[K,N] + bias[N]
// Block tile 256x64, BK=8, 256 threads, 8x8 micro-tile per thread.
// Double-buffered smem + register prefetch: one __syncthreads per k-tile,
// global loads for tile t+1 overlap the 8x68-slot compute of tile t.
// Requires 256|M, 64|N, 8|K.
// ---------------------------------------------------------------------------
#define APITCH 260   // floats; 4-float aligned; STS/LDS conflict-free (checked)
#define BKD 8

__global__ void __launch_bounds__(256, 2) gemm_kernel(
    const float* __restrict__ A, const float* __restrict__ B,
    const float* __restrict__ bias, float* __restrict__ C,
    int M, int N, int K)
{
    __shared__ float AsT[2][BKD * APITCH];  // [buf][kk*APITCH + row]
    __shared__ float Bs[2][BKD * 64];       // [buf][kk*64 + col]

    const int tid  = threadIdx.x;
    const int tx   = tid & 7;            // 8 col groups
    const int ty   = tid >> 3;           // 32 row groups
    const int ty4  = ty * 4;
    const int c0   = tx * 4;
    const int row0 = blockIdx.y << 8;
    const int col0 = blockIdx.x << 6;

    // A loader: idx = tid and tid+256 over 512 float4 chunks; r = idx>>1, kq = idx&1
    const int ar  = tid >> 1;            // 0..127 (chunk2 adds +128)
    const int akq = tid & 1;             // k-quad 0..1
    const bool bload = tid < 128;
    const int bkk = tid >> 4;            // 0..7  (tid<128)
    const int bc  = (tid & 15) * 4;      // 0..60

    const float* Arow0 = &A[(size_t)(row0 + ar) * K + akq * 4];
    const float* Arow1 = &A[(size_t)(row0 + ar + 128) * K + akq * 4];
    const float* Brow  = &B[(size_t)bkk * N + col0 + bc];

    float4 pa0, pa1, pb;
    pa0 = *(const float4*)&Arow0[0];
    pa1 = *(const float4*)&Arow1[0];
    if (bload) pb = *(const float4*)&Brow[0];

    // store prologue tile into buffer 0
    {
        float* at = &AsT[0][(akq * 4) * APITCH + ar];
        at[0 * APITCH] = pa0.x; at[1 * APITCH] = pa0.y;
        at[2 * APITCH] = pa0.z; at[3 * APITCH] = pa0.w;
        float* at1 = at + 128;
        at1[0 * APITCH] = pa1.x; at1[1 * APITCH] = pa1.y;
        at1[2 * APITCH] = pa1.z; at1[3 * APITCH] = pa1.w;
        if (bload) *(float4*)&Bs[0][bkk * 64 + bc] = pb;
    }
    __syncthreads();

    float acc[8][8];
#pragma unroll
    for (int i = 0; i < 8; ++i)
#pragma unroll
        for (int j = 0; j < 8; ++j) acc[i][j] = 0.f;

    const int T = K / BKD;
    for (int t = 0; t < T; ++t) {
        const int cur = t & 1;
        const int nxt = cur ^ 1;
        const bool more = (t + 1 < T);

        if (more) {
            const int kt = (t + 1) * BKD;
            pa0 = *(const float4*)&Arow0[kt];
            pa1 = *(const float4*)&Arow1[kt];
            if (bload) pb = *(const float4*)&Brow[(size_t)kt * N];
        }

#pragma unroll
        for (int kk = 0; kk < BKD; ++kk) {
            float4 a0 = *(const float4*)&AsT[cur][kk * APITCH + ty4];
            float4 a1 = *(const float4*)&AsT[cur][kk * APITCH + 128 + ty4];
            float4 b0 = *(const float4*)&Bs[cur][kk * 64 + c0];
            float4 b1 = *(const float4*)&Bs[cur][kk * 64 + 32 + c0];
            float av[8] = {a0.x, a0.y, a0.z, a0.w, a1.x, a1.y, a1.z, a1.w};
            float bv[8] = {b0.x, b0.y, b0.z, b0.w, b1.x, b1.y, b1.z, b1.w};
#pragma unroll
            for (int i = 0; i < 8; ++i)
#pragma unroll
                for (int j = 0; j < 8; ++j)
                    acc[i][j] += av[i] * bv[j];
        }

        if (more) {
            float* at = &AsT[nxt][(akq * 4) * APITCH + ar];
            at[0 * APITCH] = pa0.x; at[1 * APITCH] = pa0.y;
            at[2 * APITCH] = pa0.z; at[3 * APITCH] = pa0.w;
            float* at1 = at + 128;
            at1[0 * APITCH] = pa1.x; at1[1 * APITCH] = pa1.y;
            at1[2 * APITCH] = pa1.z; at1[3 * APITCH] = pa1.w;
            if (bload) *(float4*)&Bs[nxt][bkk * 64 + bc] = pb;
            __syncthreads();
        }
    }

    // ---- epilogue: + bias, store (rows ty4..+3 and +128; cols c0, c0+32)
    float4 bb0 = *(const float4*)&bias[col0 + c0];
    float4 bb1 = *(const float4*)&bias[col0 + 32 + c0];
#pragma unroll
    for (int i = 0; i < 8; ++i) {
        int r = row0 + ((i < 4) ? (ty4 + i) : (128 + ty4 + i - 4));
        float* crow = &C[(size_t)r * N + col0];
        float4 o0 = make_float4(acc[i][0] + bb0.x, acc[i][1] + bb0.y,
                                acc[i][2] + bb0.z, acc[i][3] + bb0.w);
        float4 o1 = make_float4(acc[i][4] + bb1.x, acc[i][5] + bb1.y,
                                acc[i][6] + bb1.z, acc[i][7] + bb1.w);
        *(float4*)&crow[c0]      = o0;
        *(float4*)&crow[32 + c0] = o1;
    }
}

// ---------------------------------------------------------------------------
// Pre-gather earth bias: pre[grp][head][l][m] = bias_table[pos[l][m]][grp][head]
// ---------------------------------------------------------------------------
__global__ void __launch_bounds__(256) bias_pre_kernel(
    const float* __restrict__ bt, const int* __restrict__ pos,
    float* __restrict__ pre)
{
    const int gh   = blockIdx.x;            // 0..383 = grp*6+head
    const int grp  = gh / NH;
    const int head = gh - grp * NH;
    float* dst = pre + (size_t)gh * LTOK * LTOK;
    for (int i = threadIdx.x; i < LTOK * LTOK; i += 256) {
        int pi = pos[i];
        dst[i] = bt[(size_t)pi * (TABNW * NH) + grp * NH + head];
    }
}

// ---------------------------------------------------------------------------
// Fused attention per (window, head):
//   S = scale*Q @ K^T + pre[grp,head] + mask[wi]; P = softmax(S); out = P @ V
// 256 threads = 8 warps; warp owns 18 rows in 3 passes of 6.
// Grid (NH, BWIN): 6 consecutive blocks share one window's mask -> L2 reuse.
// ---------------------------------------------------------------------------
#define QKV_PITCH 36   // Q/K/V smem row pitch (conflict-free for all patterns here)

__global__ void __launch_bounds__(256, 2) attn_kernel(
    const float* __restrict__ qkv, const float* __restrict__ mask,
    const float* __restrict__ pre, float* __restrict__ att)
{
    const int head = blockIdx.x;      // 0..5  (fast dim: heads of a window adjacent)
    const int wi   = blockIdx.y;      // 0..959
    const int grp  = wi / WWINS;
    const int tid  = threadIdx.x;
    const int w    = tid >> 5;
    const int lane = tid & 31;

    extern __shared__ float sm[];
    float* Qs = sm;                         // 144*36
    float* Ks = Qs + LTOK * QKV_PITCH;      // 144*36
    float* Vs = Ks + LTOK * QKV_PITCH;      // 144*36 (row-major [m][d])
    float* Pb = Vs + LTOK * QKV_PITCH;      // 8 warps * 6 rows * 144

    const float scale = 0.17677669529663687f;  // 32^-0.5
    const float* qbase = qkv + (size_t)wi * LTOK * (3 * CDIM) + head * HDM;

    for (int i = tid; i < LTOK * HDM; i += 256) {
        int l = i >> 5;
        int d = i & 31;
        const float* p = qbase + (size_t)l * (3 * CDIM);
        Qs[l * QKV_PITCH + d] = p[d] * scale;
        Ks[l * QKV_PITCH + d] = p[CDIM + d];
        Vs[l * QKV_PITCH + d] = p[2 * CDIM + d];
    }
    __syncthreads();

    const float* mrow = mask + (size_t)wi * LTOK * LTOK;
    const float* prow_bias = pre + (size_t)(grp * NH + head) * LTOK * LTOK;
    float* prow = Pb + w * 6 * LTOK;
    const int l0 = w * 18;

    for (int pass = 0; pass < 3; ++pass) {
        const int lbase = l0 + pass * 6;

        // ---- S = scale*Q @ K^T (6 rows x 5 m-slots per lane) ----
        float acc[6][5];
#pragma unroll
        for (int r = 0; r < 6; ++r)
#pragma unroll
            for (int j = 0; j < 5; ++j) acc[r][j] = 0.f;

#pragma unroll
        for (int dc = 0; dc < 8; ++dc) {
            float4 kv[5];
#pragma unroll
            for (int j = 0; j < 5; ++j) {
                int m = lane + 32 * j;
                kv[j] = (m < LTOK)
                    ? *(const float4*)&Ks[m * QKV_PITCH + dc * 4]
                    : make_float4(0.f, 0.f, 0.f, 0.f);
            }
#pragma unroll
            for (int r = 0; r < 6; ++r) {
                float4 qv = *(const float4*)&Qs[(lbase + r) * QKV_PITCH + dc * 4];
#pragma unroll
                for (int j = 0; j < 5; ++j) {
                    acc[r][j] += qv.x * kv[j].x + qv.y * kv[j].y
                               + qv.z * kv[j].z + qv.w * kv[j].w;
                }
            }
        }

        // ---- bias + mask + softmax per row, write P to warp buffer ----
#pragma unroll
        for (int r = 0; r < 6; ++r) {
            const int l = lbase + r;
            float s[5];
#pragma unroll
            for (int j = 0; j < 5; ++j) {
                int m = lane + 32 * j;
                if (m < LTOK) {
                    s[j] = acc[r][j] + prow_bias[l * LTOK + m] + mrow[l * LTOK + m];
                } else {
                    s[j] = -1e30f;
                }
            }
            float mx = s[0];
#pragma unroll
            for (int j = 1; j < 5; ++j) mx = fmaxf(mx, s[j]);
#pragma unroll
            for (int o = 16; o; o >>= 1)
                mx = fmaxf(mx, __shfl_xor_sync(0xffffffffu, mx, o));

            float sum = 0.f;
#pragma unroll
            for (int j = 0; j < 5; ++j) {
                float e = __expf(s[j] - mx);   // -1e30 underflows to 0
                s[j] = e;
                sum += e;
            }
#pragma unroll
            for (int o = 16; o; o >>= 1)
                sum += __shfl_xor_sync(0xffffffffu, sum, o);
            float inv = 1.0f / sum;
#pragma unroll
            for (int j = 0; j < 5; ++j) {
                int m = lane + 32 * j;
                if (m < LTOK) prow[r * LTOK + m] = s[j] * inv;
            }
        }
        __syncwarp();

        // ---- out = P @ V ; lane = output dim d ----
        float oacc[6] = {0.f, 0.f, 0.f, 0.f, 0.f, 0.f};
        for (int m = 0; m < LTOK; m += 4) {
            float v0 = Vs[(m + 0) * QKV_PITCH + lane];
            float v1 = Vs[(m + 1) * QKV_PITCH + lane];
            float v2 = Vs[(m + 2) * QKV_PITCH + lane];
            float v3 = Vs[(m + 3) * QKV_PITCH + lane];
#pragma unroll
            for (int r = 0; r < 6; ++r) {
                float4 p = *(const float4*)&prow[r * LTOK + m];
                oacc[r] += p.x * v0 + p.y * v1 + p.z * v2 + p.w * v3;
            }
        }
        float* obase = att + (size_t)wi * LTOK * CDIM + head * HDM + lane;
#pragma unroll
        for (int r = 0; r < 6; ++r)
            obase[(size_t)(lbase + r) * CDIM] = oacc[r];
        __syncwarp();   // prow reused next pass
    }
}

// ---------------------------------------------------------------------------
extern "C" void kernel_launch(void* const* d_in, const int* in_sizes, int n_in,
                              void* d_out, int out_size)
{
    const float* x          = (const float*)d_in[0];  // (960,144,192)
    const float* mask       = (const float*)d_in[1];  // (960,144,144)
    const float* W1         = (const float*)d_in[2];  // (192,576)
    const float* b1         = (const float*)d_in[3];  // (576,)
    const float* W2         = (const float*)d_in[4];  // (192,192)
    const float* b2         = (const float*)d_in[5];  // (192,)
    const float* bias_table = (const float*)d_in[6];  // (3312,64,6)
    const int*   pos        = (const int*)d_in[7];    // (144,144)
    float* out = (float*)d_out;

    void *qkv_p, *att_p, *pre_p;
    cudaGetSymbolAddress(&qkv_p, g_qkv);
    cudaGetSymbolAddress(&att_p, g_att);
    cudaGetSymbolAddress(&pre_p, g_pre);
    float* qkv = (float*)qkv_p;
    float* att = (float*)att_p;
    float* pre = (float*)pre_p;

    const int M = BWIN * LTOK;  // 138240

    const int attn_smem =
        (3 * LTOK * QKV_PITCH + 8 * 6 * LTOK) * (int)sizeof(float);  // 89856
    cudaFuncSetAttribute(attn_kernel, cudaFuncAttributeMaxDynamicSharedMemorySize, attn_smem);

    // 0) gather earth bias -> dense (grp, head, l, m)
    bias_pre_kernel<<<TABNW * NH, 256>>>(bias_table, pos, pre);

    // 1) QKV projection: (138240,192) @ (192,576) + b1
    {
        dim3 grid(3 * CDIM / 64, M / 256);  // (9, 540)
        gemm_kernel<<<grid, 256>>>(x, W1, b1, qkv, M, 3 * CDIM, CDIM);
    }
    // 2) Fused windowed attention (head = fast grid dim -> mask L2 reuse)
    {
        dim3 grid(NH, BWIN);                // (6, 960)
        attn_kernel<<<grid, 256, attn_smem>>>(qkv, mask, pre, att);
    }
    // 3) Output projection: (138240,192) @ (192,192) + b2
    {
        dim3 grid(CDIM / 64, M / 256);      // (3, 540)
        gemm_kernel<<<grid, 256>>>(att, W2, b2, out, M, CDIM, CDIM);
    }
}

// round 6
// speedup vs baseline: 2.1177x; 1.0510x over previous
#include <cuda_runtime.h>
#include <math.h>

// EarthAttention3D (Pangu-Weather windowed attention), fixed shapes:
//   B_=960 windows, L=144, C=192, HEADS=6, hd=32, W_WINS=15, NW=64
#define BWIN 960
#define LTOK 144
#define CDIM 192
#define NH   6
#define HDM  32
#define WWINS 15
#define TABNW 64

// Scratch (static device globals; no runtime allocation allowed)
__device__ float g_qkv[(size_t)BWIN * LTOK * 3 * CDIM];          // (960,144,576)
__device__ float g_att[(size_t)BWIN * LTOK * CDIM];              // (960,144,192)
__device__ float g_pre[(size_t)TABNW * NH * LTOK * LTOK];        // (64,6,144,144) gathered bias

// ---------------------------------------------------------------------------
// Scalar-FFMA GEMM (R4 version):  C[M,N] = A[M,K] @ B[K,N] + bias[N]
// Block tile 256x64, BK=16, 256 threads, 8x8 micro-tile per thread.
// ---------------------------------------------------------------------------
#define APITCH 260

__global__ void __launch_bounds__(256, 2) gemm_kernel(
    const float* __restrict__ A, const float* __restrict__ B,
    const float* __restrict__ bias, float* __restrict__ C,
    int M, int N, int K)
{
    __shared__ float AsT[16 * APITCH];   // [kk][row 0..255]
    __shared__ float Bs[16 * 64];        // [kk][col 0..63]

    const int tid  = threadIdx.x;
    const int tx   = tid & 7;
    const int ty   = tid >> 3;
    const int ty4  = ty * 4;
    const int c0   = tx * 4;
    const int row0 = blockIdx.y << 8;
    const int col0 = blockIdx.x << 6;

    float acc[8][8];
#pragma unroll
    for (int i = 0; i < 8; ++i)
#pragma unroll
        for (int j = 0; j < 8; ++j) acc[i][j] = 0.f;

    const int bkk = tid >> 4;
    const int bc  = (tid & 15) * 4;

    for (int kt = 0; kt < K; kt += 16) {
#pragma unroll
        for (int ch = 0; ch < 4; ++ch) {
            int idx = tid + (ch << 8);
            int r   = idx >> 2;
            int kq  = idx & 3;
            float4 a = *(const float4*)&A[(size_t)(row0 + r) * K + kt + kq * 4];
            AsT[(kq * 4 + 0) * APITCH + r] = a.x;
            AsT[(kq * 4 + 1) * APITCH + r] = a.y;
            AsT[(kq * 4 + 2) * APITCH + r] = a.z;
            AsT[(kq * 4 + 3) * APITCH + r] = a.w;
        }
        *(float4*)&Bs[bkk * 64 + bc] =
            *(const float4*)&B[(size_t)(kt + bkk) * N + col0 + bc];
        __syncthreads();

#pragma unroll
        for (int kk = 0; kk < 16; ++kk) {
            float4 a0 = *(const float4*)&AsT[kk * APITCH + ty4];
            float4 a1 = *(const float4*)&AsT[kk * APITCH + 128 + ty4];
            float4 b0 = *(const float4*)&Bs[kk * 64 + c0];
            float4 b1 = *(const float4*)&Bs[kk * 64 + 32 + c0];
            float av[8] = {a0.x, a0.y, a0.z, a0.w, a1.x, a1.y, a1.z, a1.w};
            float bv[8] = {b0.x, b0.y, b0.z, b0.w, b1.x, b1.y, b1.z, b1.w};
#pragma unroll
            for (int i = 0; i < 8; ++i)
#pragma unroll
                for (int j = 0; j < 8; ++j)
                    acc[i][j] += av[i] * bv[j];
        }
        __syncthreads();
    }

    float4 bb0 = *(const float4*)&bias[col0 + c0];
    float4 bb1 = *(const float4*)&bias[col0 + 32 + c0];
#pragma unroll
    for (int i = 0; i < 8; ++i) {
        int r = row0 + ((i < 4) ? (ty4 + i) : (128 + ty4 + i - 4));
        float* crow = &C[(size_t)r * N + col0];
        float4 o0 = make_float4(acc[i][0] + bb0.x, acc[i][1] + bb0.y,
                                acc[i][2] + bb0.z, acc[i][3] + bb0.w);
        float4 o1 = make_float4(acc[i][4] + bb1.x, acc[i][5] + bb1.y,
                                acc[i][6] + bb1.z, acc[i][7] + bb1.w);
        *(float4*)&crow[c0]      = o0;
        *(float4*)&crow[32 + c0] = o1;
    }
}

// ---------------------------------------------------------------------------
// Pre-gather earth bias: pre[grp][head][l][m] = bias_table[pos[l][m]][grp][head]
// ---------------------------------------------------------------------------
__global__ void __launch_bounds__(256) bias_pre_kernel(
    const float* __restrict__ bt, const int* __restrict__ pos,
    float* __restrict__ pre)
{
    const int gh   = blockIdx.x;
    const int grp  = gh / NH;
    const int head = gh - grp * NH;
    float* dst = pre + (size_t)gh * LTOK * LTOK;
    for (int i = threadIdx.x; i < LTOK * LTOK; i += 256) {
        int pi = pos[i];
        dst[i] = bt[(size_t)pi * (TABNW * NH) + grp * NH + head];
    }
}

// ---------------------------------------------------------------------------
// Fused attention per (window, head).
// K stored TRANSPOSED in smem (KT[d][m], pitch 145) -> conflict-free QK reads.
// ---------------------------------------------------------------------------
#define Q_PITCH 36    // Q/V smem row pitch
#define KT_PITCH 145  // K^T row pitch: stores bank-stride 17 (coprime 32), reads stride 1

__global__ void __launch_bounds__(256, 2) attn_kernel(
    const float* __restrict__ qkv, const float* __restrict__ mask,
    const float* __restrict__ pre, float* __restrict__ att)
{
    const int head = blockIdx.x;      // fast dim: 6 heads of a window adjacent (mask L2 reuse)
    const int wi   = blockIdx.y;
    const int grp  = wi / WWINS;
    const int tid  = threadIdx.x;
    const int w    = tid >> 5;
    const int lane = tid & 31;

    extern __shared__ float sm[];
    float* Qs = sm;                          // 144*36
    float* KT = Qs + LTOK * Q_PITCH;         // 32*145 (K transposed [d][m])
    float* Vs = KT + HDM * KT_PITCH;         // 144*36 (row-major [m][d])
    float* Pb = Vs + LTOK * Q_PITCH;         // 8 warps * 6 rows * 144

    const float scale = 0.17677669529663687f;  // 32^-0.5
    const float* qbase = qkv + (size_t)wi * LTOK * (3 * CDIM) + head * HDM;

    for (int i = tid; i < LTOK * HDM; i += 256) {
        int l = i >> 5;
        int d = i & 31;
        const float* p = qbase + (size_t)l * (3 * CDIM);
        Qs[l * Q_PITCH + d]   = p[d] * scale;
        KT[d * KT_PITCH + l]  = p[CDIM + d];
        Vs[l * Q_PITCH + d]   = p[2 * CDIM + d];
    }
    __syncthreads();

    const float* mrow = mask + (size_t)wi * LTOK * LTOK;
    const float* prow_bias = pre + (size_t)(grp * NH + head) * LTOK * LTOK;
    float* prow = Pb + w * 6 * LTOK;
    const int l0 = w * 18;

    for (int pass = 0; pass < 3; ++pass) {
        const int lbase = l0 + pass * 6;

        // ---- S = scale*Q @ K^T (6 rows x 5 m-slots per lane) ----
        float acc[6][5];
#pragma unroll
        for (int r = 0; r < 6; ++r)
#pragma unroll
            for (int j = 0; j < 5; ++j) acc[r][j] = 0.f;

#pragma unroll
        for (int dc = 0; dc < 8; ++dc) {
            // K columns for 4 head-dims, 5 m-slots: lane-stride-1, conflict-free
            float kt[4][5];
#pragma unroll
            for (int t = 0; t < 4; ++t) {
                const float* krow = &KT[(dc * 4 + t) * KT_PITCH];
#pragma unroll
                for (int j = 0; j < 5; ++j) {
                    int m = lane + 32 * j;
                    kt[t][j] = (m < LTOK) ? krow[m] : 0.f;
                }
            }
#pragma unroll
            for (int r = 0; r < 6; ++r) {
                float4 qv = *(const float4*)&Qs[(lbase + r) * Q_PITCH + dc * 4];
#pragma unroll
                for (int j = 0; j < 5; ++j) {
                    acc[r][j] += qv.x * kt[0][j] + qv.y * kt[1][j]
                               + qv.z * kt[2][j] + qv.w * kt[3][j];
                }
            }
        }

        // ---- bias + mask + softmax per row, write P to warp buffer ----
#pragma unroll
        for (int r = 0; r < 6; ++r) {
            const int l = lbase + r;
            float s[5];
#pragma unroll
            for (int j = 0; j < 5; ++j) {
                int m = lane + 32 * j;
                if (m < LTOK) {
                    s[j] = acc[r][j] + prow_bias[l * LTOK + m] + mrow[l * LTOK + m];
                } else {
                    s[j] = -1e30f;
                }
            }
            float mx = s[0];
#pragma unroll
            for (int j = 1; j < 5; ++j) mx = fmaxf(mx, s[j]);
#pragma unroll
            for (int o = 16; o; o >>= 1)
                mx = fmaxf(mx, __shfl_xor_sync(0xffffffffu, mx, o));

            float sum = 0.f;
#pragma unroll
            for (int j = 0; j < 5; ++j) {
                float e = __expf(s[j] - mx);   // -1e30 underflows to 0
                s[j] = e;
                sum += e;
            }
#pragma unroll
            for (int o = 16; o; o >>= 1)
                sum += __shfl_xor_sync(0xffffffffu, sum, o);
            float inv = 1.0f / sum;
#pragma unroll
            for (int j = 0; j < 5; ++j) {
                int m = lane + 32 * j;
                if (m < LTOK) prow[r * LTOK + m] = s[j] * inv;
            }
        }
        __syncwarp();

        // ---- out = P @ V ; lane = output dim d ----
        float oacc[6] = {0.f, 0.f, 0.f, 0.f, 0.f, 0.f};
        for (int m = 0; m < LTOK; m += 4) {
            float v0 = Vs[(m + 0) * Q_PITCH + lane];
            float v1 = Vs[(m + 1) * Q_PITCH + lane];
            float v2 = Vs[(m + 2) * Q_PITCH + lane];
            float v3 = Vs[(m + 3) * Q_PITCH + lane];
#pragma unroll
            for (int r = 0; r < 6; ++r) {
                float4 p = *(const float4*)&prow[r * LTOK + m];
                oacc[r] += p.x * v0 + p.y * v1 + p.z * v2 + p.w * v3;
            }
        }
        float* obase = att + (size_t)wi * LTOK * CDIM + head * HDM + lane;
#pragma unroll
        for (int r = 0; r < 6; ++r)
            obase[(size_t)(lbase + r) * CDIM] = oacc[r];
        __syncwarp();   // prow reused next pass
    }
}

// ---------------------------------------------------------------------------
extern "C" void kernel_launch(void* const* d_in, const int* in_sizes, int n_in,
                              void* d_out, int out_size)
{
    const float* x          = (const float*)d_in[0];
    const float* mask       = (const float*)d_in[1];
    const float* W1         = (const float*)d_in[2];
    const float* b1         = (const float*)d_in[3];
    const float* W2         = (const float*)d_in[4];
    const float* b2         = (const float*)d_in[5];
    const float* bias_table = (const float*)d_in[6];
    const int*   pos        = (const int*)d_in[7];
    float* out = (float*)d_out;

    void *qkv_p, *att_p, *pre_p;
    cudaGetSymbolAddress(&qkv_p, g_qkv);
    cudaGetSymbolAddress(&att_p, g_att);
    cudaGetSymbolAddress(&pre_p, g_pre);
    float* qkv = (float*)qkv_p;
    float* att = (float*)att_p;
    float* pre = (float*)pre_p;

    const int M = BWIN * LTOK;  // 138240

    const int attn_smem =
        (2 * LTOK * Q_PITCH + HDM * KT_PITCH + 8 * 6 * LTOK) * (int)sizeof(float);
    cudaFuncSetAttribute(attn_kernel, cudaFuncAttributeMaxDynamicSharedMemorySize, attn_smem);

    // 0) gather earth bias -> dense (grp, head, l, m)
    bias_pre_kernel<<<TABNW * NH, 256>>>(bias_table, pos, pre);

    // 1) QKV projection: (138240,192) @ (192,576) + b1
    {
        dim3 grid(3 * CDIM / 64, M / 256);  // (9, 540)
        gemm_kernel<<<grid, 256>>>(x, W1, b1, qkv, M, 3 * CDIM, CDIM);
    }
    // 2) Fused windowed attention (head = fast grid dim -> mask L2 reuse)
    {
        dim3 grid(NH, BWIN);                // (6, 960)
        attn_kernel<<<grid, 256, attn_smem>>>(qkv, mask, pre, att);
    }
    // 3) Output projection: (138240,192) @ (192,192) + b2
    {
        dim3 grid(CDIM / 64, M / 256);      // (3, 540)
        gemm_kernel<<<grid, 256>>>(att, W2, b2, out, M, CDIM, CDIM);
    }
}